// round 1
// baseline (speedup 1.0000x reference)
#include <cuda_runtime.h>
#include <cstdint>

#define NB 64
#define NN 22
#define NF 64
#define NO 64
#define NT 512
#define NK 3
#define TT 8              // t-tile width per CTA
#define KM (NK*NN)        // 66
#define A2P 24            // padded n pitch for A2 rows

typedef unsigned long long u64;

__device__ float d_S[NK*NN*NN];        // Chebyshev supports
__device__ float d_A2[NB*KM*A2P];      // per-batch folded coefficients

// ---------------------------------------------------------------------------
// packed f32x2 helpers (Blackwell)
// ---------------------------------------------------------------------------
__device__ __forceinline__ u64 pk2(float a, float b) {
    u64 r; asm("mov.b64 %0,{%1,%2};" : "=l"(r) : "f"(a), "f"(b)); return r;
}
__device__ __forceinline__ u64 ffma2(u64 a, u64 b, u64 c) {
    u64 d; asm("fma.rn.f32x2 %0,%1,%2,%3;" : "=l"(d) : "l"(a), "l"(b), "l"(c)); return d;
}
__device__ __forceinline__ void unpk(u64 v, float& a, float& b) {
    asm("mov.b64 {%0,%1},%2;" : "=f"(a), "=f"(b) : "l"(v));
}

// ---------------------------------------------------------------------------
// K0: supports = softmax(relu(E E^T), axis=1); Cheb S0=I, S1=supports,
//     S2 = 2*S1@S1 - I.  Single block, 32 threads (rows 0..21 active).
// ---------------------------------------------------------------------------
__global__ void k_supports(const float* __restrict__ E) {
    __shared__ float sup[NN][NN];
    int i = threadIdx.x;
    if (i < NN) {
        float p[NN];
        float mx = -1e30f;
        #pragma unroll
        for (int j = 0; j < NN; j++) {
            float s = 0.f;
            #pragma unroll
            for (int l = 0; l < NN; l++) s += E[i*NN + l] * E[j*NN + l];
            s = fmaxf(s, 0.f);
            p[j] = s;
            mx = fmaxf(mx, s);
        }
        float den = 0.f;
        #pragma unroll
        for (int j = 0; j < NN; j++) { p[j] = expf(p[j] - mx); den += p[j]; }
        float inv = 1.f / den;
        #pragma unroll
        for (int j = 0; j < NN; j++) sup[i][j] = p[j] * inv;
    }
    __syncthreads();
    if (i < NN) {
        #pragma unroll
        for (int j = 0; j < NN; j++) {
            float eye = (i == j) ? 1.f : 0.f;
            d_S[0*NN*NN + i*NN + j] = eye;
            d_S[1*NN*NN + i*NN + j] = sup[i][j];
            float s = 0.f;
            #pragma unroll
            for (int l = 0; l < NN; l++) s += sup[i][l] * sup[l][j];
            d_S[2*NN*NN + i*NN + j] = 2.f * s - eye;
        }
    }
}

// ---------------------------------------------------------------------------
// K1: A2[b][k*22+m][n] = S[k][n][m] * att[b][n][m]   (pad n to 24 with zeros)
// ---------------------------------------------------------------------------
__global__ void k_a2(const float* __restrict__ att) {
    int b = blockIdx.x;
    for (int idx = threadIdx.x; idx < KM*A2P; idx += blockDim.x) {
        int km = idx / A2P, nn = idx % A2P;
        int k = km / NN, m = km % NN;
        float v = 0.f;
        if (nn < NN) v = d_S[k*NN*NN + nn*NN + m] * att[(b*NN + nn)*NN + m];
        d_A2[b*KM*A2P + idx] = v;
    }
}

// ---------------------------------------------------------------------------
// Main fused kernel: one CTA per (b, 8-wide t tile). 768 threads.
// Phase 1: rhs[k][m][f][t] = sum_n A2[km][n]*x[b][n][f][t]   (SMEM)
// Phase 2: out[b][m][o][t] = relu(sum_{k,f} theta[k][f][o]*rhs[k][m][f][t])
// ---------------------------------------------------------------------------
__global__ void __launch_bounds__(768, 1) k_main(
    const float* __restrict__ x,
    const float* __restrict__ theta_g,
    float* __restrict__ out)
{
    extern __shared__ float sm[];
    float* theta_s = sm;                          // [192][64]   = 12288 f
    float* rhs_s   = sm + NK*NF*NO;               // [66][64*8]  = 33792 f
    float* a2_s    = rhs_s + KM*NF*TT;            // [66][24]    = 1584 f

    const int tid = threadIdx.x;
    const int b   = blockIdx.y;
    const int tt0 = blockIdx.x * TT;

    // --- stage-in theta and A2 ---
    {
        const float4* tg = (const float4*)theta_g;
        float4* ts = (float4*)theta_s;
        #pragma unroll
        for (int j = 0; j < 4; j++) ts[tid + j*768] = tg[tid + j*768];
        if (tid < (KM*A2P)/4)
            ((float4*)a2_s)[tid] = ((const float4*)(d_A2 + b*KM*A2P))[tid];
    }
    __syncthreads();

    // --- phase 1: each thread does 2 items (k,f,t); 3*64*8 = 1536 items ---
    const float* xb = x + (size_t)b*NN*NF*NT + tt0;
    #pragma unroll
    for (int it = 0; it < 2; it++) {
        int item = tid + it*768;
        int k = item >> 9;          // 512 items per k -> warp-uniform
        int f = (item >> 3) & 63;
        int t = item & 7;
        float acc[NN];
        if (k == 0) {
            // S0 = I  ->  only n == m contributes
            #pragma unroll
            for (int m = 0; m < NN; m++)
                acc[m] = a2_s[m*A2P + m] * xb[(m*NF + f)*NT + t];
        } else {
            #pragma unroll
            for (int m = 0; m < NN; m++) acc[m] = 0.f;
            #pragma unroll
            for (int c = 0; c < 5; c++) {
                float xv0 = xb[((c*4+0)*NF + f)*NT + t];
                float xv1 = xb[((c*4+1)*NF + f)*NT + t];
                float xv2 = xb[((c*4+2)*NF + f)*NT + t];
                float xv3 = xb[((c*4+3)*NF + f)*NT + t];
                #pragma unroll
                for (int m = 0; m < NN; m++) {
                    float4 a = *(const float4*)&a2_s[(k*NN + m)*A2P + c*4];
                    acc[m] = fmaf(a.x, xv0, acc[m]);
                    acc[m] = fmaf(a.y, xv1, acc[m]);
                    acc[m] = fmaf(a.z, xv2, acc[m]);
                    acc[m] = fmaf(a.w, xv3, acc[m]);
                }
            }
            {   // tail n = 20, 21
                float xv0 = xb[(20*NF + f)*NT + t];
                float xv1 = xb[(21*NF + f)*NT + t];
                #pragma unroll
                for (int m = 0; m < NN; m++) {
                    float2 a = *(const float2*)&a2_s[(k*NN + m)*A2P + 20];
                    acc[m] = fmaf(a.x, xv0, acc[m]);
                    acc[m] = fmaf(a.y, xv1, acc[m]);
                }
            }
        }
        #pragma unroll
        for (int m = 0; m < NN; m++)
            rhs_s[(k*NN + m)*(NF*TT) + f*TT + t] = acc[m];
    }
    __syncthreads();

    // --- phase 2: warp <-> m; lane tile 4o x 4t; packed f32x2 FMAs ---
    const int wid = tid >> 5;
    if (wid < NN) {
        const int m    = wid;
        const int lane = tid & 31;
        const int o0   = (lane >> 1) * 4;   // 16 o-blocks of 4
        const int tb   = (lane & 1) * 4;    // 2 t-halves of 4

        u64 z = pk2(0.f, 0.f);
        u64 a01[4] = {z, z, z, z};          // outputs (o0, o0+1) x t[0..3]
        u64 a23[4] = {z, z, z, z};          // outputs (o0+2, o0+3) x t[0..3]

        #pragma unroll
        for (int k = 0; k < NK; k++) {
            const float* rr = rhs_s + (k*NN + m)*(NF*TT) + tb;
            const float* tr = theta_s + k*NF*NO + o0;
            #pragma unroll 8
            for (int f = 0; f < NF; f++) {
                float4 tv = *(const float4*)(tr + f*NO);
                float4 rv = *(const float4*)(rr + f*TT);
                u64 t01 = pk2(tv.x, tv.y);
                u64 t23 = pk2(tv.z, tv.w);
                u64 r0 = pk2(rv.x, rv.x);
                u64 r1 = pk2(rv.y, rv.y);
                u64 r2 = pk2(rv.z, rv.z);
                u64 r3 = pk2(rv.w, rv.w);
                a01[0] = ffma2(t01, r0, a01[0]);  a23[0] = ffma2(t23, r0, a23[0]);
                a01[1] = ffma2(t01, r1, a01[1]);  a23[1] = ffma2(t23, r1, a23[1]);
                a01[2] = ffma2(t01, r2, a01[2]);  a23[2] = ffma2(t23, r2, a23[2]);
                a01[3] = ffma2(t01, r3, a01[3]);  a23[3] = ffma2(t23, r3, a23[3]);
            }
        }

        // epilogue: unpack, relu, vectorized store
        float r0l[4], r0h[4], r1l[4], r1h[4];
        #pragma unroll
        for (int j = 0; j < 4; j++) {
            unpk(a01[j], r0l[j], r0h[j]);
            unpk(a23[j], r1l[j], r1h[j]);
        }
        float* op = out + ((size_t)(b*NN + m)*NO + o0)*NT + tt0 + tb;
        *(float4*)(op + 0*NT) = make_float4(fmaxf(r0l[0],0.f), fmaxf(r0l[1],0.f),
                                            fmaxf(r0l[2],0.f), fmaxf(r0l[3],0.f));
        *(float4*)(op + 1*NT) = make_float4(fmaxf(r0h[0],0.f), fmaxf(r0h[1],0.f),
                                            fmaxf(r0h[2],0.f), fmaxf(r0h[3],0.f));
        *(float4*)(op + 2*NT) = make_float4(fmaxf(r1l[0],0.f), fmaxf(r1l[1],0.f),
                                            fmaxf(r1l[2],0.f), fmaxf(r1l[3],0.f));
        *(float4*)(op + 3*NT) = make_float4(fmaxf(r1h[0],0.f), fmaxf(r1h[1],0.f),
                                            fmaxf(r1h[2],0.f), fmaxf(r1h[3],0.f));
    }
}

// ---------------------------------------------------------------------------
extern "C" void kernel_launch(void* const* d_in, const int* in_sizes, int n_in,
                              void* d_out, int out_size)
{
    const float* x     = (const float*)d_in[0];   // [B,N,F_in,T]
    const float* att   = (const float*)d_in[1];   // [B,N,N]
    const float* theta = (const float*)d_in[2];   // [K,F_in,F_out]
    const float* emb   = (const float*)d_in[3];   // [N,N]
    float* out = (float*)d_out;                   // [B,N,F_out,T]

    k_supports<<<1, 32>>>(emb);
    k_a2<<<NB, 256>>>(att);

    size_t smem = (size_t)(NK*NF*NO + KM*NF*TT + KM*A2P) * sizeof(float);
    cudaFuncSetAttribute(k_main, cudaFuncAttributeMaxDynamicSharedMemorySize, (int)smem);
    dim3 grid(NT/TT, NB);
    k_main<<<grid, 768, smem>>>(x, theta, out);
}

// round 2
// speedup vs baseline: 1.0010x; 1.0010x over previous
#include <cuda_runtime.h>
#include <cstdint>

#define NB 64
#define NN 22
#define NF 64
#define NO 64
#define NT 512
#define NK 3
#define TT 8              // t-tile width per CTA
#define KM (NK*NN)        // 66
#define A2P 24            // padded n pitch for A2 rows

typedef unsigned long long u64;

__device__ float d_S[NK*NN*NN];        // Chebyshev supports
__device__ float d_A2[NB*KM*A2P];      // per-batch folded coefficients

// ---------------------------------------------------------------------------
// packed f32x2 helpers (Blackwell)
// ---------------------------------------------------------------------------
__device__ __forceinline__ u64 pk2(float a, float b) {
    u64 r; asm("mov.b64 %0,{%1,%2};" : "=l"(r) : "f"(a), "f"(b)); return r;
}
__device__ __forceinline__ u64 ffma2(u64 a, u64 b, u64 c) {
    u64 d; asm("fma.rn.f32x2 %0,%1,%2,%3;" : "=l"(d) : "l"(a), "l"(b), "l"(c)); return d;
}
__device__ __forceinline__ void unpk(u64 v, float& a, float& b) {
    asm("mov.b64 {%0,%1},%2;" : "=f"(a), "=f"(b) : "l"(v));
}

// ---------------------------------------------------------------------------
// K0: supports = softmax(relu(E E^T), axis=1); Cheb S0=I, S1=supports,
//     S2 = 2*S1@S1 - I.  Single block, 32 threads (rows 0..21 active).
// ---------------------------------------------------------------------------
__global__ void k_supports(const float* __restrict__ E) {
    __shared__ float sup[NN][NN];
    int i = threadIdx.x;
    if (i < NN) {
        float p[NN];
        float mx = -1e30f;
        #pragma unroll
        for (int j = 0; j < NN; j++) {
            float s = 0.f;
            #pragma unroll
            for (int l = 0; l < NN; l++) s += E[i*NN + l] * E[j*NN + l];
            s = fmaxf(s, 0.f);
            p[j] = s;
            mx = fmaxf(mx, s);
        }
        float den = 0.f;
        #pragma unroll
        for (int j = 0; j < NN; j++) { p[j] = expf(p[j] - mx); den += p[j]; }
        float inv = 1.f / den;
        #pragma unroll
        for (int j = 0; j < NN; j++) sup[i][j] = p[j] * inv;
    }
    __syncthreads();
    if (i < NN) {
        #pragma unroll
        for (int j = 0; j < NN; j++) {
            float eye = (i == j) ? 1.f : 0.f;
            d_S[0*NN*NN + i*NN + j] = eye;
            d_S[1*NN*NN + i*NN + j] = sup[i][j];
            float s = 0.f;
            #pragma unroll
            for (int l = 0; l < NN; l++) s += sup[i][l] * sup[l][j];
            d_S[2*NN*NN + i*NN + j] = 2.f * s - eye;
        }
    }
}

// ---------------------------------------------------------------------------
// K1: A2[b][k*22+m][n] = S[k][n][m] * att[b][n][m]   (pad n to 24 with zeros)
// ---------------------------------------------------------------------------
__global__ void k_a2(const float* __restrict__ att) {
    int b = blockIdx.x;
    for (int idx = threadIdx.x; idx < KM*A2P; idx += blockDim.x) {
        int km = idx / A2P, nn = idx % A2P;
        int k = km / NN, m = km % NN;
        float v = 0.f;
        if (nn < NN) v = d_S[k*NN*NN + nn*NN + m] * att[(b*NN + nn)*NN + m];
        d_A2[b*KM*A2P + idx] = v;
    }
}

// ---------------------------------------------------------------------------
// Main fused kernel: one CTA per (b, 8-wide t tile). 768 threads.
// Phase 1: rhs[k][m][f][t] = sum_n A2[km][n]*x[b][n][f][t]   (SMEM)
// Phase 2: out[b][m][o][t] = relu(sum_{k,f} theta[k][f][o]*rhs[k][m][f][t])
// ---------------------------------------------------------------------------
__global__ void __launch_bounds__(768, 1) k_main(
    const float* __restrict__ x,
    const float* __restrict__ theta_g,
    float* __restrict__ out)
{
    extern __shared__ float sm[];
    float* theta_s = sm;                          // [192][64]   = 12288 f
    float* rhs_s   = sm + NK*NF*NO;               // [66][64*8]  = 33792 f
    float* a2_s    = rhs_s + KM*NF*TT;            // [66][24]    = 1584 f

    const int tid = threadIdx.x;
    const int b   = blockIdx.y;
    const int tt0 = blockIdx.x * TT;

    // --- stage-in theta and A2 ---
    {
        const float4* tg = (const float4*)theta_g;
        float4* ts = (float4*)theta_s;
        #pragma unroll
        for (int j = 0; j < 4; j++) ts[tid + j*768] = tg[tid + j*768];
        if (tid < (KM*A2P)/4)
            ((float4*)a2_s)[tid] = ((const float4*)(d_A2 + b*KM*A2P))[tid];
    }
    __syncthreads();

    // --- phase 1: each thread does 2 items (k,f,t); 3*64*8 = 1536 items ---
    const float* xb = x + (size_t)b*NN*NF*NT + tt0;
    #pragma unroll
    for (int it = 0; it < 2; it++) {
        int item = tid + it*768;
        int k = item >> 9;          // 512 items per k -> warp-uniform
        int f = (item >> 3) & 63;
        int t = item & 7;
        float acc[NN];
        if (k == 0) {
            // S0 = I  ->  only n == m contributes
            #pragma unroll
            for (int m = 0; m < NN; m++)
                acc[m] = a2_s[m*A2P + m] * xb[(m*NF + f)*NT + t];
        } else {
            #pragma unroll
            for (int m = 0; m < NN; m++) acc[m] = 0.f;
            #pragma unroll
            for (int c = 0; c < 5; c++) {
                float xv0 = xb[((c*4+0)*NF + f)*NT + t];
                float xv1 = xb[((c*4+1)*NF + f)*NT + t];
                float xv2 = xb[((c*4+2)*NF + f)*NT + t];
                float xv3 = xb[((c*4+3)*NF + f)*NT + t];
                #pragma unroll
                for (int m = 0; m < NN; m++) {
                    float4 a = *(const float4*)&a2_s[(k*NN + m)*A2P + c*4];
                    acc[m] = fmaf(a.x, xv0, acc[m]);
                    acc[m] = fmaf(a.y, xv1, acc[m]);
                    acc[m] = fmaf(a.z, xv2, acc[m]);
                    acc[m] = fmaf(a.w, xv3, acc[m]);
                }
            }
            {   // tail n = 20, 21
                float xv0 = xb[(20*NF + f)*NT + t];
                float xv1 = xb[(21*NF + f)*NT + t];
                #pragma unroll
                for (int m = 0; m < NN; m++) {
                    float2 a = *(const float2*)&a2_s[(k*NN + m)*A2P + 20];
                    acc[m] = fmaf(a.x, xv0, acc[m]);
                    acc[m] = fmaf(a.y, xv1, acc[m]);
                }
            }
        }
        #pragma unroll
        for (int m = 0; m < NN; m++)
            rhs_s[(k*NN + m)*(NF*TT) + f*TT + t] = acc[m];
    }
    __syncthreads();

    // --- phase 2: warp <-> m; lane tile 4o x 4t; packed f32x2 FMAs ---
    const int wid = tid >> 5;
    if (wid < NN) {
        const int m    = wid;
        const int lane = tid & 31;
        const int o0   = (lane >> 1) * 4;   // 16 o-blocks of 4
        const int tb   = (lane & 1) * 4;    // 2 t-halves of 4

        u64 z = pk2(0.f, 0.f);
        u64 a01[4] = {z, z, z, z};          // outputs (o0, o0+1) x t[0..3]
        u64 a23[4] = {z, z, z, z};          // outputs (o0+2, o0+3) x t[0..3]

        #pragma unroll
        for (int k = 0; k < NK; k++) {
            const float* rr = rhs_s + (k*NN + m)*(NF*TT) + tb;
            const float* tr = theta_s + k*NF*NO + o0;
            #pragma unroll 8
            for (int f = 0; f < NF; f++) {
                float4 tv = *(const float4*)(tr + f*NO);
                float4 rv = *(const float4*)(rr + f*TT);
                u64 t01 = pk2(tv.x, tv.y);
                u64 t23 = pk2(tv.z, tv.w);
                u64 r0 = pk2(rv.x, rv.x);
                u64 r1 = pk2(rv.y, rv.y);
                u64 r2 = pk2(rv.z, rv.z);
                u64 r3 = pk2(rv.w, rv.w);
                a01[0] = ffma2(t01, r0, a01[0]);  a23[0] = ffma2(t23, r0, a23[0]);
                a01[1] = ffma2(t01, r1, a01[1]);  a23[1] = ffma2(t23, r1, a23[1]);
                a01[2] = ffma2(t01, r2, a01[2]);  a23[2] = ffma2(t23, r2, a23[2]);
                a01[3] = ffma2(t01, r3, a01[3]);  a23[3] = ffma2(t23, r3, a23[3]);
            }
        }

        // epilogue: unpack, relu, vectorized store
        float r0l[4], r0h[4], r1l[4], r1h[4];
        #pragma unroll
        for (int j = 0; j < 4; j++) {
            unpk(a01[j], r0l[j], r0h[j]);
            unpk(a23[j], r1l[j], r1h[j]);
        }
        float* op = out + ((size_t)(b*NN + m)*NO + o0)*NT + tt0 + tb;
        *(float4*)(op + 0*NT) = make_float4(fmaxf(r0l[0],0.f), fmaxf(r0l[1],0.f),
                                            fmaxf(r0l[2],0.f), fmaxf(r0l[3],0.f));
        *(float4*)(op + 1*NT) = make_float4(fmaxf(r0h[0],0.f), fmaxf(r0h[1],0.f),
                                            fmaxf(r0h[2],0.f), fmaxf(r0h[3],0.f));
        *(float4*)(op + 2*NT) = make_float4(fmaxf(r1l[0],0.f), fmaxf(r1l[1],0.f),
                                            fmaxf(r1l[2],0.f), fmaxf(r1l[3],0.f));
        *(float4*)(op + 3*NT) = make_float4(fmaxf(r1h[0],0.f), fmaxf(r1h[1],0.f),
                                            fmaxf(r1h[2],0.f), fmaxf(r1h[3],0.f));
    }
}

// ---------------------------------------------------------------------------
extern "C" void kernel_launch(void* const* d_in, const int* in_sizes, int n_in,
                              void* d_out, int out_size)
{
    const float* x     = (const float*)d_in[0];   // [B,N,F_in,T]
    const float* att   = (const float*)d_in[1];   // [B,N,N]
    const float* theta = (const float*)d_in[2];   // [K,F_in,F_out]
    const float* emb   = (const float*)d_in[3];   // [N,N]
    float* out = (float*)d_out;                   // [B,N,F_out,T]

    k_supports<<<1, 32>>>(emb);
    k_a2<<<NB, 256>>>(att);

    size_t smem = (size_t)(NK*NF*NO + KM*NF*TT + KM*A2P) * sizeof(float);
    cudaFuncSetAttribute(k_main, cudaFuncAttributeMaxDynamicSharedMemorySize, (int)smem);
    dim3 grid(NT/TT, NB);
    k_main<<<grid, 768, smem>>>(x, theta, out);
}